// round 1
// baseline (speedup 1.0000x reference)
#include <cuda_runtime.h>
#include <cstdint>
#include <math.h>

// ---------------- problem constants ----------------
#define NN 50000        // nodes
#define EE 1600000      // edges
#define FD 48           // out dim
#define HD 256          // hidden / in dim
#define KHOP 10

// ---------------- device scratch (allocation-free rule: __device__ globals) ----
__device__ int   g_is64;
__device__ int   g_src[EE];
__device__ int   g_dst[EE];
__device__ int   g_deg[NN];
__device__ float g_dinv[NN];
__device__ int   g_offs[NN + 1];
__device__ int   g_cursor[NN];
__device__ int   g_col[EE];
__device__ float g_w[EE];
__device__ float g_h1[(size_t)NN * HD];     // relu(x@W1+b1)
__device__ float g_hk0[(size_t)NN * FD];
__device__ float g_hk1[(size_t)NN * FD];
__device__ float g_hidden[(size_t)NN * FD];

// ---------------- dtype detection for edge_index (int64 vs int32) -------------
__global__ void detect_kernel(const void* ei) {
    if (threadIdx.x == 0 && blockIdx.x == 0) {
        const long long* p = (const long long*)ei;
        int ok = 1;
        for (int i = 0; i < 64; i++) {
            long long v = p[i];
            if (v < 0 || v >= NN) { ok = 0; break; }
        }
        g_is64 = ok;
    }
}

__global__ void init_deg_kernel() {
    int i = blockIdx.x * blockDim.x + threadIdx.x;
    if (i < NN) g_deg[i] = 1;   // self-loop contributes 1 to in-degree
}

// read edges (either dtype), store int32 src/dst, histogram dst
__global__ void convert_count_kernel(const void* ei) {
    int e = blockIdx.x * blockDim.x + threadIdx.x;
    if (e >= EE) return;
    int s, d;
    if (g_is64) {
        const long long* p = (const long long*)ei;
        s = (int)p[e];
        d = (int)p[(size_t)EE + e];
    } else {
        const int* p = (const int*)ei;
        s = p[e];
        d = p[EE + e];
    }
    g_src[e] = s;
    g_dst[e] = d;
    atomicAdd(&g_deg[d], 1);
}

__global__ void dinv_kernel() {
    int i = blockIdx.x * blockDim.x + threadIdx.x;
    if (i < NN) g_dinv[i] = rsqrtf((float)g_deg[i]);
}

// single-block exclusive scan over (deg-1) -> offs, cursor
__global__ void scan_kernel() {
    __shared__ int sh[1024];
    int carry = 0;
    for (int base = 0; base < NN; base += 1024) {
        int i = base + threadIdx.x;
        int v = (i < NN) ? (g_deg[i] - 1) : 0;
        sh[threadIdx.x] = v;
        __syncthreads();
        for (int off = 1; off < 1024; off <<= 1) {
            int t = (threadIdx.x >= off) ? sh[threadIdx.x - off] : 0;
            __syncthreads();
            sh[threadIdx.x] += t;
            __syncthreads();
        }
        int incl = sh[threadIdx.x];
        if (i < NN) {
            int excl = carry + incl - v;
            g_offs[i] = excl;
            g_cursor[i] = excl;
        }
        carry += sh[1023];
        __syncthreads();
    }
    if (threadIdx.x == 0) g_offs[NN] = carry;
}

__global__ void scatter_kernel() {
    int e = blockIdx.x * blockDim.x + threadIdx.x;
    if (e >= EE) return;
    int s = g_src[e];
    int d = g_dst[e];
    int pos = atomicAdd(&g_cursor[d], 1);
    g_col[pos] = s;
    g_w[pos] = g_dinv[s] * g_dinv[d];
}

// ---------------- SGEMM1: h1 = relu(x @ W1 + b1), [NN,256]x[256,256] -------
// BM=128 BN=128 BK=8, 256 threads, 8x8 per thread
__global__ void sgemm1_kernel(const float* __restrict__ A,
                              const float* __restrict__ B,
                              const float* __restrict__ bias) {
    __shared__ float As[8][128];
    __shared__ float Bs[8][128];
    int tid = threadIdx.x;
    int bm = blockIdx.y * 128;
    int bn = blockIdx.x * 128;
    int tx = tid & 15;   // col group
    int ty = tid >> 4;   // row group
    float acc[8][8];
#pragma unroll
    for (int i = 0; i < 8; i++)
#pragma unroll
        for (int j = 0; j < 8; j++) acc[i][j] = 0.f;

    int arow = tid >> 1;
    int acol = (tid & 1) * 4;
    int brow = tid >> 5;
    int bcol = (tid & 31) * 4;

    for (int k0 = 0; k0 < HD; k0 += 8) {
        float4 av;
        if (bm + arow < NN)
            av = *(const float4*)&A[(size_t)(bm + arow) * HD + k0 + acol];
        else
            av = make_float4(0.f, 0.f, 0.f, 0.f);
        As[acol + 0][arow] = av.x;
        As[acol + 1][arow] = av.y;
        As[acol + 2][arow] = av.z;
        As[acol + 3][arow] = av.w;
        float4 bv = *(const float4*)&B[(size_t)(k0 + brow) * 256 + bn + bcol];
        *(float4*)&Bs[brow][bcol] = bv;
        __syncthreads();
#pragma unroll
        for (int kk = 0; kk < 8; kk++) {
            float a[8], b[8];
            float4 a0 = *(float4*)&As[kk][ty * 8];
            float4 a1 = *(float4*)&As[kk][ty * 8 + 4];
            float4 b0 = *(float4*)&Bs[kk][tx * 8];
            float4 b1 = *(float4*)&Bs[kk][tx * 8 + 4];
            a[0]=a0.x; a[1]=a0.y; a[2]=a0.z; a[3]=a0.w;
            a[4]=a1.x; a[5]=a1.y; a[6]=a1.z; a[7]=a1.w;
            b[0]=b0.x; b[1]=b0.y; b[2]=b0.z; b[3]=b0.w;
            b[4]=b1.x; b[5]=b1.y; b[6]=b1.z; b[7]=b1.w;
#pragma unroll
            for (int i = 0; i < 8; i++)
#pragma unroll
                for (int j = 0; j < 8; j++) acc[i][j] += a[i] * b[j];
        }
        __syncthreads();
    }
#pragma unroll
    for (int i = 0; i < 8; i++) {
        int row = bm + ty * 8 + i;
        if (row < NN) {
#pragma unroll
            for (int j = 0; j < 8; j++) {
                int col = bn + tx * 8 + j;
                float v = acc[i][j] + bias[col];
                g_h1[(size_t)row * HD + col] = v > 0.f ? v : 0.f;
            }
        }
    }
}

// ---------------- SGEMM2: hk0 = h1 @ W2 + b2 ; hidden = temp[0]*hk0 -------
// BM=128 BN=48 BK=16, 256 threads (16x16), 8x3 per thread
__global__ void sgemm2_kernel(const float* __restrict__ B,     // W2 [256,48]
                              const float* __restrict__ bias,  // b2 [48]
                              const float* __restrict__ temp) {
    __shared__ float As[16][128];
    __shared__ float Bs[16][48];
    int tid = threadIdx.x;
    int bm = blockIdx.x * 128;
    int tx = tid & 15;
    int ty = tid >> 4;
    float acc[8][3];
#pragma unroll
    for (int i = 0; i < 8; i++)
#pragma unroll
        for (int j = 0; j < 3; j++) acc[i][j] = 0.f;

    int arow = tid >> 1;
    int acol = (tid & 1) * 8;

    for (int k0 = 0; k0 < HD; k0 += 16) {
        // A tile (transposed): 128 rows x 16 k
        float4 av0, av1;
        if (bm + arow < NN) {
            av0 = *(const float4*)&g_h1[(size_t)(bm + arow) * HD + k0 + acol];
            av1 = *(const float4*)&g_h1[(size_t)(bm + arow) * HD + k0 + acol + 4];
        } else {
            av0 = make_float4(0.f, 0.f, 0.f, 0.f);
            av1 = av0;
        }
        As[acol + 0][arow] = av0.x; As[acol + 1][arow] = av0.y;
        As[acol + 2][arow] = av0.z; As[acol + 3][arow] = av0.w;
        As[acol + 4][arow] = av1.x; As[acol + 5][arow] = av1.y;
        As[acol + 6][arow] = av1.z; As[acol + 7][arow] = av1.w;
        // B tile: 16 x 48
        for (int i = tid; i < 16 * 48; i += 256) {
            int r = i / 48, c = i - r * 48;
            Bs[r][c] = B[(size_t)(k0 + r) * 48 + c];
        }
        __syncthreads();
#pragma unroll
        for (int kk = 0; kk < 16; kk++) {
            float a[8];
            float4 a0 = *(float4*)&As[kk][ty * 8];
            float4 a1 = *(float4*)&As[kk][ty * 8 + 4];
            a[0]=a0.x; a[1]=a0.y; a[2]=a0.z; a[3]=a0.w;
            a[4]=a1.x; a[5]=a1.y; a[6]=a1.z; a[7]=a1.w;
            float b0 = Bs[kk][tx * 3 + 0];
            float b1 = Bs[kk][tx * 3 + 1];
            float b2v = Bs[kk][tx * 3 + 2];
#pragma unroll
            for (int i = 0; i < 8; i++) {
                acc[i][0] += a[i] * b0;
                acc[i][1] += a[i] * b1;
                acc[i][2] += a[i] * b2v;
            }
        }
        __syncthreads();
    }
    float t0 = temp[0];
#pragma unroll
    for (int i = 0; i < 8; i++) {
        int row = bm + ty * 8 + i;
        if (row < NN) {
#pragma unroll
            for (int j = 0; j < 3; j++) {
                int col = tx * 3 + j;
                float v = acc[i][j] + bias[col];
                g_hk0[(size_t)row * FD + col] = v;
                g_hidden[(size_t)row * FD + col] = t0 * v;
            }
        }
    }
}

// ---------------- SpMM hop: next = A_norm @ cur ; hidden += temp[k]*next ----
// one warp per dst node; lane covers col lane and (lane<16) col lane+32
__global__ void spmm_kernel(const float* __restrict__ temp, int k, int parity) {
    const float* __restrict__ cur  = parity ? g_hk1 : g_hk0;
    float*       __restrict__ next = parity ? g_hk0 : g_hk1;
    int warp = (blockIdx.x * blockDim.x + threadIdx.x) >> 5;
    int lane = threadIdx.x & 31;
    if (warp >= NN) return;
    int d = warp;
    int s0 = g_offs[d];
    int s1 = g_offs[d + 1];
    float acc0 = 0.f, acc1 = 0.f;
    for (int e = s0; e < s1; e += 32) {
        int idx = 0;
        float wv = 0.f;
        if (e + lane < s1) {
            idx = g_col[e + lane];
            wv = g_w[e + lane];
        }
        int cnt = min(32, s1 - e);
        for (int j = 0; j < cnt; j++) {
            int   s  = __shfl_sync(0xffffffffu, idx, j);
            float ww = __shfl_sync(0xffffffffu, wv, j);
            const float* row = cur + (size_t)s * FD;
            acc0 += ww * row[lane];
            if (lane < 16) acc1 += ww * row[32 + lane];
        }
    }
    // self loop
    float di = g_dinv[d];
    float sw = di * di;
    const float* srow = cur + (size_t)d * FD;
    acc0 += sw * srow[lane];
    if (lane < 16) acc1 += sw * srow[32 + lane];

    float t = temp[k];
    size_t base = (size_t)d * FD;
    next[base + lane] = acc0;
    g_hidden[base + lane] += t * acc0;
    if (lane < 16) {
        next[base + 32 + lane] = acc1;
        g_hidden[base + 32 + lane] += t * acc1;
    }
}

// ---------------- log_softmax over 48 cols, warp per row --------------------
__global__ void logsoftmax_kernel(float* __restrict__ out) {
    int warp = (blockIdx.x * blockDim.x + threadIdx.x) >> 5;
    int lane = threadIdx.x & 31;
    if (warp >= NN) return;
    size_t base = (size_t)warp * FD;
    float v0 = g_hidden[base + lane];
    float v1 = (lane < 16) ? g_hidden[base + 32 + lane] : -INFINITY;
    float m = fmaxf(v0, v1);
#pragma unroll
    for (int off = 16; off > 0; off >>= 1)
        m = fmaxf(m, __shfl_xor_sync(0xffffffffu, m, off));
    float s = expf(v0 - m) + ((lane < 16) ? expf(v1 - m) : 0.f);
#pragma unroll
    for (int off = 16; off > 0; off >>= 1)
        s += __shfl_xor_sync(0xffffffffu, s, off);
    float l = m + logf(s);
    out[base + lane] = v0 - l;
    if (lane < 16) out[base + 32 + lane] = v1 - l;
}

// ---------------- launch ----------------------------------------------------
extern "C" void kernel_launch(void* const* d_in, const int* in_sizes, int n_in,
                              void* d_out, int out_size) {
    const float* x    = (const float*)d_in[0];
    const void*  ei   = d_in[1];
    const float* W1   = (const float*)d_in[2];
    const float* b1   = (const float*)d_in[3];
    const float* W2   = (const float*)d_in[4];
    const float* b2   = (const float*)d_in[5];
    const float* temp = (const float*)d_in[6];
    float* out = (float*)d_out;

    detect_kernel<<<1, 32>>>(ei);
    init_deg_kernel<<<(NN + 255) / 256, 256>>>();
    convert_count_kernel<<<(EE + 255) / 256, 256>>>(ei);
    dinv_kernel<<<(NN + 255) / 256, 256>>>();
    scan_kernel<<<1, 1024>>>();
    scatter_kernel<<<(EE + 255) / 256, 256>>>();

    dim3 g1(2, (NN + 127) / 128);
    sgemm1_kernel<<<g1, 256>>>(x, W1, b1);
    sgemm2_kernel<<<(NN + 127) / 128, 256>>>(W2, b2, temp);

    int spmm_blocks = (NN * 32 + 255) / 256;  // warp per node, 8 warps/block
    for (int k = 1; k <= KHOP; k++) {
        spmm_kernel<<<spmm_blocks, 256>>>(temp, k, (k - 1) & 1);
    }
    logsoftmax_kernel<<<(NN * 32 + 255) / 256, 256>>>(out);
}

// round 3
// speedup vs baseline: 1.1993x; 1.1993x over previous
#include <cuda_runtime.h>
#include <cstdint>
#include <math.h>

// ---------------- problem constants ----------------
#define NN 50000        // nodes
#define EE 1600000      // edges
#define FD 48           // out dim
#define HD 256          // hidden / in dim
#define KHOP 10

// ---------------- device scratch (allocation-free rule: __device__ globals) ----
__device__ int   g_is64;
__device__ int   g_src[EE];
__device__ int   g_dst[EE];
__device__ int   g_deg[NN];
__device__ float g_dinv[NN];
__device__ int   g_offs[NN + 1];
__device__ int   g_cursor[NN];
__device__ int2  g_cw[EE];                  // packed (col, weight-bits)
__device__ float g_h1[(size_t)NN * HD];     // relu(x@W1+b1)
__device__ float g_hk0[(size_t)NN * FD];
__device__ float g_hk1[(size_t)NN * FD];
__device__ float g_hidden[(size_t)NN * FD];

// ---------------- detect edge dtype + init degrees (launch 1) ---------------
__global__ void detect_init_kernel(const void* ei) {
    int i = blockIdx.x * blockDim.x + threadIdx.x;
    if (i < NN) g_deg[i] = 1;   // self-loop contributes 1 to in-degree
    if (i == 0) {
        const long long* p = (const long long*)ei;
        int ok = 1;
        for (int j = 0; j < 64; j++) {
            long long v = p[j];
            if (v < 0 || v >= NN) { ok = 0; break; }
        }
        g_is64 = ok;
    }
}

// read edges (either dtype), store int32 src/dst, histogram dst (launch 2)
__global__ void convert_count_kernel(const void* ei) {
    int e = blockIdx.x * blockDim.x + threadIdx.x;
    if (e >= EE) return;
    int s, d;
    if (g_is64) {
        const long long* p = (const long long*)ei;
        s = (int)p[e];
        d = (int)p[(size_t)EE + e];
    } else {
        const int* p = (const int*)ei;
        s = p[e];
        d = p[EE + e];
    }
    g_src[e] = s;
    g_dst[e] = d;
    atomicAdd(&g_deg[d], 1);
}

// single-block exclusive scan over (deg-1) -> offs, cursor; also dinv (launch 3)
__global__ void scan_kernel() {
    __shared__ int sh[1024];
    int carry = 0;
    for (int base = 0; base < NN; base += 1024) {
        int i = base + threadIdx.x;
        int deg = (i < NN) ? g_deg[i] : 1;
        int v = deg - 1;
        if (i < NN) g_dinv[i] = rsqrtf((float)deg);
        sh[threadIdx.x] = v;
        __syncthreads();
        for (int off = 1; off < 1024; off <<= 1) {
            int t = (threadIdx.x >= off) ? sh[threadIdx.x - off] : 0;
            __syncthreads();
            sh[threadIdx.x] += t;
            __syncthreads();
        }
        int incl = sh[threadIdx.x];
        if (i < NN) {
            int excl = carry + incl - v;
            g_offs[i] = excl;
            g_cursor[i] = excl;
        }
        carry += sh[1023];
        __syncthreads();
    }
    if (threadIdx.x == 0) g_offs[NN] = carry;
}

// ---------------- SGEMM1: h1 = relu(x @ W1 + b1) (launch 4) ----------------
// BM=128 BN=128 BK=16, 256 threads, 8x8 per thread, double-buffered smem
__global__ void sgemm1_kernel(const float* __restrict__ A,
                              const float* __restrict__ B,
                              const float* __restrict__ bias) {
    __shared__ float As[2][16][128];
    __shared__ float Bs[2][16][128];
    int tid = threadIdx.x;
    int bm = blockIdx.y * 128;
    int bn = blockIdx.x * 128;
    int tx = tid & 15;
    int ty = tid >> 4;
    int arow = tid >> 1;
    int acol = (tid & 1) * 8;
    int brow = tid >> 4;          // 0..15
    int bcol = (tid & 15) * 8;    // 0..120

    float acc[8][8];
#pragma unroll
    for (int i = 0; i < 8; i++)
#pragma unroll
        for (int j = 0; j < 8; j++) acc[i][j] = 0.f;

    float4 ra0, ra1, rb0, rb1;

    // prefetch tile 0
    {
        if (bm + arow < NN) {
            ra0 = *(const float4*)&A[(size_t)(bm + arow) * HD + 0 + acol];
            ra1 = *(const float4*)&A[(size_t)(bm + arow) * HD + 0 + acol + 4];
        } else {
            ra0 = make_float4(0.f, 0.f, 0.f, 0.f); ra1 = ra0;
        }
        rb0 = *(const float4*)&B[(size_t)(0 + brow) * 256 + bn + bcol];
        rb1 = *(const float4*)&B[(size_t)(0 + brow) * 256 + bn + bcol + 4];
    }
    // store stage 0
    As[0][acol + 0][arow] = ra0.x; As[0][acol + 1][arow] = ra0.y;
    As[0][acol + 2][arow] = ra0.z; As[0][acol + 3][arow] = ra0.w;
    As[0][acol + 4][arow] = ra1.x; As[0][acol + 5][arow] = ra1.y;
    As[0][acol + 6][arow] = ra1.z; As[0][acol + 7][arow] = ra1.w;
    *(float4*)&Bs[0][brow][bcol] = rb0;
    *(float4*)&Bs[0][brow][bcol + 4] = rb1;
    __syncthreads();

    int buf = 0;
    for (int k0 = 0; k0 < HD; k0 += 16) {
        int knext = k0 + 16;
        if (knext < HD) {
            if (bm + arow < NN) {
                ra0 = *(const float4*)&A[(size_t)(bm + arow) * HD + knext + acol];
                ra1 = *(const float4*)&A[(size_t)(bm + arow) * HD + knext + acol + 4];
            } else {
                ra0 = make_float4(0.f, 0.f, 0.f, 0.f); ra1 = ra0;
            }
            rb0 = *(const float4*)&B[(size_t)(knext + brow) * 256 + bn + bcol];
            rb1 = *(const float4*)&B[(size_t)(knext + brow) * 256 + bn + bcol + 4];
        }
#pragma unroll
        for (int kk = 0; kk < 16; kk++) {
            float a[8], b[8];
            float4 a0 = *(float4*)&As[buf][kk][ty * 8];
            float4 a1 = *(float4*)&As[buf][kk][ty * 8 + 4];
            float4 b0 = *(float4*)&Bs[buf][kk][tx * 8];
            float4 b1 = *(float4*)&Bs[buf][kk][tx * 8 + 4];
            a[0]=a0.x; a[1]=a0.y; a[2]=a0.z; a[3]=a0.w;
            a[4]=a1.x; a[5]=a1.y; a[6]=a1.z; a[7]=a1.w;
            b[0]=b0.x; b[1]=b0.y; b[2]=b0.z; b[3]=b0.w;
            b[4]=b1.x; b[5]=b1.y; b[6]=b1.z; b[7]=b1.w;
#pragma unroll
            for (int i = 0; i < 8; i++)
#pragma unroll
                for (int j = 0; j < 8; j++) acc[i][j] += a[i] * b[j];
        }
        if (knext < HD) {
            int nb = buf ^ 1;
            As[nb][acol + 0][arow] = ra0.x; As[nb][acol + 1][arow] = ra0.y;
            As[nb][acol + 2][arow] = ra0.z; As[nb][acol + 3][arow] = ra0.w;
            As[nb][acol + 4][arow] = ra1.x; As[nb][acol + 5][arow] = ra1.y;
            As[nb][acol + 6][arow] = ra1.z; As[nb][acol + 7][arow] = ra1.w;
            *(float4*)&Bs[nb][brow][bcol] = rb0;
            *(float4*)&Bs[nb][brow][bcol + 4] = rb1;
            __syncthreads();
            buf = nb;
        }
    }
#pragma unroll
    for (int i = 0; i < 8; i++) {
        int row = bm + ty * 8 + i;
        if (row < NN) {
#pragma unroll
            for (int j = 0; j < 8; j++) {
                int col = bn + tx * 8 + j;
                float v = acc[i][j] + bias[col];
                g_h1[(size_t)row * HD + col] = v > 0.f ? v : 0.f;
            }
        }
    }
}

// ---------------- scatter into CSR with packed (col,w) (launch 5) -----------
__global__ void scatter_kernel() {
    int e = blockIdx.x * blockDim.x + threadIdx.x;
    if (e >= EE) return;
    int s = g_src[e];
    int d = g_dst[e];
    int pos = atomicAdd(&g_cursor[d], 1);
    float w = g_dinv[s] * g_dinv[d];
    g_cw[pos] = make_int2(s, __float_as_int(w));
}

// ---------------- SGEMM2: hk0 = h1 @ W2 + b2 ; hidden = temp[0]*hk0 (launch 6)
__global__ void sgemm2_kernel(const float* __restrict__ B,     // W2 [256,48]
                              const float* __restrict__ bias,  // b2 [48]
                              const float* __restrict__ temp) {
    __shared__ float As[16][128];
    __shared__ float Bs[16][48];
    int tid = threadIdx.x;
    int bm = blockIdx.x * 128;
    int tx = tid & 15;
    int ty = tid >> 4;
    float acc[8][3];
#pragma unroll
    for (int i = 0; i < 8; i++)
#pragma unroll
        for (int j = 0; j < 3; j++) acc[i][j] = 0.f;

    int arow = tid >> 1;
    int acol = (tid & 1) * 8;

    for (int k0 = 0; k0 < HD; k0 += 16) {
        float4 av0, av1;
        if (bm + arow < NN) {
            av0 = *(const float4*)&g_h1[(size_t)(bm + arow) * HD + k0 + acol];
            av1 = *(const float4*)&g_h1[(size_t)(bm + arow) * HD + k0 + acol + 4];
        } else {
            av0 = make_float4(0.f, 0.f, 0.f, 0.f);
            av1 = av0;
        }
        As[acol + 0][arow] = av0.x; As[acol + 1][arow] = av0.y;
        As[acol + 2][arow] = av0.z; As[acol + 3][arow] = av0.w;
        As[acol + 4][arow] = av1.x; As[acol + 5][arow] = av1.y;
        As[acol + 6][arow] = av1.z; As[acol + 7][arow] = av1.w;
        for (int i = tid; i < 16 * 48; i += 256) {
            int r = i / 48, c = i - r * 48;
            Bs[r][c] = B[(size_t)(k0 + r) * 48 + c];
        }
        __syncthreads();
#pragma unroll
        for (int kk = 0; kk < 16; kk++) {
            float a[8];
            float4 a0 = *(float4*)&As[kk][ty * 8];
            float4 a1 = *(float4*)&As[kk][ty * 8 + 4];
            a[0]=a0.x; a[1]=a0.y; a[2]=a0.z; a[3]=a0.w;
            a[4]=a1.x; a[5]=a1.y; a[6]=a1.z; a[7]=a1.w;
            float b0 = Bs[kk][tx * 3 + 0];
            float b1 = Bs[kk][tx * 3 + 1];
            float b2v = Bs[kk][tx * 3 + 2];
#pragma unroll
            for (int i = 0; i < 8; i++) {
                acc[i][0] += a[i] * b0;
                acc[i][1] += a[i] * b1;
                acc[i][2] += a[i] * b2v;
            }
        }
        __syncthreads();
    }
    float t0 = temp[0];
#pragma unroll
    for (int i = 0; i < 8; i++) {
        int row = bm + ty * 8 + i;
        if (row < NN) {
#pragma unroll
            for (int j = 0; j < 3; j++) {
                int col = tx * 3 + j;
                float v = acc[i][j] + bias[col];
                g_hk0[(size_t)row * FD + col] = v;
                g_hidden[(size_t)row * FD + col] = t0 * v;
            }
        }
    }
}

// ---------------- SpMM hop: feature-parallel, float4 per thread -------------
// 12 threads per dst node (12 x float4 = 48 floats). Edge (col,w) packed in
// g_cw; 4-edge unroll for MLP. next = A_norm @ cur ; hidden += temp[k]*next.
__global__ void spmm_kernel(const float* __restrict__ temp, int k, int parity) {
    const float* __restrict__ cur  = parity ? g_hk1 : g_hk0;
    float*       __restrict__ next = parity ? g_hk0 : g_hk1;
    int t = blockIdx.x * blockDim.x + threadIdx.x;
    if (t >= NN * 12) return;
    int d = t / 12;
    int q = t - d * 12;            // float4 slot within row
    const float4* __restrict__ curv = (const float4*)cur;

    int e0 = g_offs[d];
    int e1 = g_offs[d + 1];
    float ax = 0.f, ay = 0.f, az = 0.f, aw = 0.f;

    int e = e0;
    for (; e + 4 <= e1; e += 4) {
        int2 c0 = g_cw[e + 0];
        int2 c1 = g_cw[e + 1];
        int2 c2 = g_cw[e + 2];
        int2 c3 = g_cw[e + 3];
        float4 v0 = __ldg(&curv[c0.x * 12 + q]);
        float4 v1 = __ldg(&curv[c1.x * 12 + q]);
        float4 v2 = __ldg(&curv[c2.x * 12 + q]);
        float4 v3 = __ldg(&curv[c3.x * 12 + q]);
        float w0 = __int_as_float(c0.y);
        float w1 = __int_as_float(c1.y);
        float w2 = __int_as_float(c2.y);
        float w3 = __int_as_float(c3.y);
        ax += w0 * v0.x + w1 * v1.x + w2 * v2.x + w3 * v3.x;
        ay += w0 * v0.y + w1 * v1.y + w2 * v2.y + w3 * v3.y;
        az += w0 * v0.z + w1 * v1.z + w2 * v2.z + w3 * v3.z;
        aw += w0 * v0.w + w1 * v1.w + w2 * v2.w + w3 * v3.w;
    }
    for (; e < e1; e++) {
        int2 c0 = g_cw[e];
        float4 v0 = __ldg(&curv[c0.x * 12 + q]);
        float w0 = __int_as_float(c0.y);
        ax += w0 * v0.x; ay += w0 * v0.y; az += w0 * v0.z; aw += w0 * v0.w;
    }
    // self loop
    float di = g_dinv[d];
    float sw = di * di;
    float4 sv = __ldg(&curv[d * 12 + q]);
    ax += sw * sv.x; ay += sw * sv.y; az += sw * sv.z; aw += sw * sv.w;

    float tk = temp[k];
    float4* nextv = (float4*)next;
    float4* hidv  = (float4*)g_hidden;
    float4 hv = hidv[t];
    hv.x += tk * ax; hv.y += tk * ay; hv.z += tk * az; hv.w += tk * aw;
    nextv[t] = make_float4(ax, ay, az, aw);
    hidv[t] = hv;
}

// ---------------- log_softmax over 48 cols, warp per row --------------------
__global__ void logsoftmax_kernel(float* __restrict__ out) {
    int warp = (blockIdx.x * blockDim.x + threadIdx.x) >> 5;
    int lane = threadIdx.x & 31;
    if (warp >= NN) return;
    size_t base = (size_t)warp * FD;
    float v0 = g_hidden[base + lane];
    float v1 = (lane < 16) ? g_hidden[base + 32 + lane] : -INFINITY;
    float m = fmaxf(v0, v1);
#pragma unroll
    for (int off = 16; off > 0; off >>= 1)
        m = fmaxf(m, __shfl_xor_sync(0xffffffffu, m, off));
    float s = expf(v0 - m) + ((lane < 16) ? expf(v1 - m) : 0.f);
#pragma unroll
    for (int off = 16; off > 0; off >>= 1)
        s += __shfl_xor_sync(0xffffffffu, s, off);
    float l = m + logf(s);
    out[base + lane] = v0 - l;
    if (lane < 16) out[base + 32 + lane] = v1 - l;
}

// ---------------- launch ----------------------------------------------------
extern "C" void kernel_launch(void* const* d_in, const int* in_sizes, int n_in,
                              void* d_out, int out_size) {
    const float* x    = (const float*)d_in[0];
    const void*  ei   = d_in[1];
    const float* W1   = (const float*)d_in[2];
    const float* b1   = (const float*)d_in[3];
    const float* W2   = (const float*)d_in[4];
    const float* b2   = (const float*)d_in[5];
    const float* temp = (const float*)d_in[6];
    float* out = (float*)d_out;

    detect_init_kernel<<<(NN + 255) / 256, 256>>>(ei);          // 1
    convert_count_kernel<<<(EE + 255) / 256, 256>>>(ei);        // 2
    scan_kernel<<<1, 1024>>>();                                 // 3 (offs+dinv)

    dim3 g1(2, (NN + 127) / 128);
    sgemm1_kernel<<<g1, 256>>>(x, W1, b1);                      // 4

    scatter_kernel<<<(EE + 255) / 256, 256>>>();                // 5
    sgemm2_kernel<<<(NN + 127) / 128, 256>>>(W2, b2, temp);     // 6

    int spmm_threads = NN * 12;
    int spmm_blocks = (spmm_threads + 255) / 256;
    for (int k = 1; k <= KHOP; k++) {
        spmm_kernel<<<spmm_blocks, 256>>>(temp, k, (k - 1) & 1);
    }
    logsoftmax_kernel<<<(NN * 32 + 255) / 256, 256>>>(out);
}